// round 13
// baseline (speedup 1.0000x reference)
#include <cuda_runtime.h>
#include <cstdint>
#include <cstddef>
#include <math.h>

#define Bb 32
#define Tt 1024
#define Dd 512
#define Hh 512
#define R4 4096
#define NBLK 128
#define NTHR 256
#define PREB 148

__device__ float    g_P[(size_t)Tt * R4 * Bb];   // [t][r][b], r = cell*2048+gate*512+j
__device__ float    g_H[2][2][Hh/4][Bb][4];      // [pp][cell][j/4][b][j&3]
__device__ float    g_XH[2][Tt][Bb];
__device__ unsigned g_bar;
__device__ unsigned g_pcnt[Tt];                  // pre tiles completed per t (target 32)

__device__ __forceinline__ float fsig(float x) {
    x = fminf(fmaxf(x, -30.0f), 30.0f);
    return __fdividef(1.0f, 1.0f + __expf(-x));
}
__device__ __forceinline__ float ftanh(float x) {
    x = fminf(fmaxf(x, -15.0f), 15.0f);
    float e = __expf(2.0f * x);
    return __fdividef(e - 1.0f, e + 1.0f);
}
__device__ __forceinline__ float4 ldcg4(const float4* p) {
    float4 v;
    asm volatile("ld.global.cg.v4.f32 {%0,%1,%2,%3},[%4];"
                 : "=f"(v.x), "=f"(v.y), "=f"(v.z), "=f"(v.w) : "l"(p));
    return v;
}
__device__ __forceinline__ void stcg2(float2* p, float2 v) {
    asm volatile("st.global.cg.v2.f32 [%0],{%1,%2};" :: "l"(p), "f"(v.x), "f"(v.y));
}
__device__ __forceinline__ float ldcg1(const float* p) {
    float v; asm volatile("ld.global.cg.f32 %0,[%1];" : "=f"(v) : "l"(p)); return v;
}

// =====================================================================
// Kernel 1: PERSISTENT producer. 148 blocks (1/SM), each loops tiles in
// t-ascending order; co-resides with rec_kernel and fills idle FMA slots.
// P[t][r][b] = sum_d U[b][t][d]*Wih[r][d] + bih[r] + bhh[r]
// =====================================================================
__global__ __launch_bounds__(256) void pre_kernel(
    const float* __restrict__ U,
    const float* __restrict__ wih_f, const float* __restrict__ wih_b,
    const float* __restrict__ bih_f, const float* __restrict__ bhh_f,
    const float* __restrict__ bih_b, const float* __restrict__ bhh_b)
{
    __shared__ float Us[32][36];
    __shared__ float Ws[32][132];

    const int tid = threadIdx.x;
    const int b0  = (tid & 7) * 4;
    const int rr0 = ((tid >> 3) & 31) * 4;
    const int bb  = tid >> 3;
    const int kq  = tid & 7;

    for (int tile = blockIdx.x; tile < 32 * Tt; tile += PREB) {
        const int t  = tile >> 5;
        const int r0 = (tile & 31) * 128;
        const int cb = (r0 >= 2048);
        const float* wih = cb ? wih_b : wih_f;
        const int rbase = r0 - cb * 2048;

        float acc[4][4];
#pragma unroll
        for (int i = 0; i < 4; ++i)
#pragma unroll
            for (int j = 0; j < 4; ++j) acc[i][j] = 0.0f;

        for (int kt = 0; kt < 16; ++kt) {
            const int k0 = kt * 32;
            {
                float4 v = *(const float4*)&U[(size_t)bb * (Tt * Dd) + (size_t)t * Dd + k0 + kq * 4];
                Us[kq * 4 + 0][bb] = v.x; Us[kq * 4 + 1][bb] = v.y;
                Us[kq * 4 + 2][bb] = v.z; Us[kq * 4 + 3][bb] = v.w;
            }
#pragma unroll
            for (int ii = 0; ii < 4; ++ii) {
                int rr = (tid >> 3) + 32 * ii;
                float4 v = *(const float4*)&wih[(size_t)(rbase + rr) * Dd + k0 + kq * 4];
                Ws[kq * 4 + 0][rr] = v.x; Ws[kq * 4 + 1][rr] = v.y;
                Ws[kq * 4 + 2][rr] = v.z; Ws[kq * 4 + 3][rr] = v.w;
            }
            __syncthreads();
#pragma unroll
            for (int k = 0; k < 32; ++k) {
                float4 ub = *(const float4*)&Us[k][b0];
                float4 wr = *(const float4*)&Ws[k][rr0];
                acc[0][0] += wr.x*ub.x; acc[0][1] += wr.x*ub.y; acc[0][2] += wr.x*ub.z; acc[0][3] += wr.x*ub.w;
                acc[1][0] += wr.y*ub.x; acc[1][1] += wr.y*ub.y; acc[1][2] += wr.y*ub.z; acc[1][3] += wr.y*ub.w;
                acc[2][0] += wr.z*ub.x; acc[2][1] += wr.z*ub.y; acc[2][2] += wr.z*ub.z; acc[2][3] += wr.z*ub.w;
                acc[3][0] += wr.w*ub.x; acc[3][1] += wr.w*ub.y; acc[3][2] += wr.w*ub.z; acc[3][3] += wr.w*ub.w;
            }
            __syncthreads();
        }
#pragma unroll
        for (int i = 0; i < 4; ++i) {
            int rw = rbase + rr0 + i;
            float bias = cb ? (bih_b[rw] + bhh_b[rw]) : (bih_f[rw] + bhh_f[rw]);
            float4 o = make_float4(acc[i][0]+bias, acc[i][1]+bias, acc[i][2]+bias, acc[i][3]+bias);
            *(float4*)&g_P[((size_t)t * R4 + (size_t)(r0 + rr0 + i)) * Bb + b0] = o;
        }
        // publish this tile
        __threadfence();
        __syncthreads();
        if (tid == 0) atomicAdd(&g_pcnt[t], 1u);
    }
}

// =====================================================================
// Kernel 2: persistent recurrence; waits on g_pcnt[t]==32 before P[t].
// =====================================================================
__global__ void __launch_bounds__(NTHR, 1) rec_kernel(
    const float* __restrict__ whh_f, const float* __restrict__ whh_b,
    const float* __restrict__ wih_f, const float* __restrict__ wih_b)
{
    extern __shared__ char smraw[];
    float*  ws   = (float*)smraw;                 // [32 rows][512]  row = p*8+u*4+gate
    float4* hs   = (float4*)(smraw + 65536);      // [128 kq][32 b]
    float*  redA = (float*)(smraw + 131072);      // [8 w][8 q][32 b]
    float*  rsum = redA + 8*8*32;                 // [32]
    float*  red  = rsum + 32;                     // [256]

    const int tid  = threadIdx.x;
    const int w    = tid >> 5;
    const int p    = w & 3;
    const int kh   = w >> 2;
    const int b    = tid & 31;
    const int cell = blockIdx.x >> 6;
    const int g    = blockIdx.x & 63;
    const int jA   = g * 8 + 2 * p;

    const float* whh = cell ? whh_b : whh_f;
    const float* wih = cell ? wih_b : wih_f;

    for (int idx = tid * 4; idx < 32 * 512; idx += NTHR * 4) {
        int rl = idx >> 9, k = idx & 511;
        int p_ = rl >> 3, q = rl & 7, u = q >> 2, gate = q & 3;
        int grow = gate * 512 + g * 8 + 2 * p_ + u;
        *(float4*)&ws[idx] = *(const float4*)&whh[(size_t)grow * 512 + k];
    }
    {   // rowsums of Wih (sub-step-2 scalar-broadcast projection)
        int rl = tid & 31, part = tid >> 5;
        int p_ = rl >> 3, q = rl & 7, u = q >> 2, gate = q & 3;
        int grow = gate * 512 + g * 8 + 2 * p_ + u;
        float s = 0.0f;
        const float* pp = &wih[(size_t)grow * 512 + part * 64];
#pragma unroll 4
        for (int k = 0; k < 64; k += 4) {
            float4 v = *(const float4*)&pp[k];
            s += v.x + v.y + v.z + v.w;
        }
        red[tid] = s;
    }
    __syncthreads();
    if (tid < 32) {
        float s = 0.0f;
#pragma unroll
        for (int q = 0; q < 8; ++q) s += red[tid + 32 * q];
        rsum[tid] = s;
    }
    __syncthreads();
    float rs[8];
#pragma unroll
    for (int q = 0; q < 8; ++q) rs[q] = rsum[p * 8 + q];

    float cst[2] = {0.0f, 0.0f};
    const float4* wr4 = (const float4*)(ws + (p * 8) * 512);
    const bool is_xh = (cell == 1 && jA + 1 == Hh - 1);

    for (int step = 0; step < 2 * Tt; ++step) {
        const int t = step >> 1, sub = step & 1;
        const int rbuf = step & 1, wbuf = rbuf ^ 1;

        // wait until all 32 producer tiles of P[t] have published
        if (sub == 0) {
            if (tid == 0) {
                unsigned v;
                do {
                    asm volatile("ld.acquire.gpu.global.u32 %0,[%1];"
                                 : "=r"(v) : "l"(&g_pcnt[t]));
                } while (v < 32u);
            }
            __syncthreads();
        }

        float pv[8];
        if (kh == 0) {
            const float* Pt = g_P + ((size_t)t * R4 + (size_t)cell * 2048) * Bb;
#pragma unroll
            for (int q = 0; q < 8; ++q) {
                int u = q >> 2, gate = q & 3;
                pv[q] = ldcg1(&Pt[(size_t)(gate * 512 + jA + u) * Bb + b]);
            }
        }
        float xh = (sub && kh == 0) ? ldcg1(&g_H[rbuf][1][(Hh - 1) >> 2][b][3]) : 0.0f;

        if (step == 0) {
            float4 z = make_float4(0.f, 0.f, 0.f, 0.f);
            for (int i = tid; i < 128 * 32; i += NTHR) hs[i] = z;
        } else {
            const float4* src = (const float4*)&g_H[rbuf][cell][0][0][0];
            for (int i = tid; i < 128 * 32; i += NTHR) hs[i] = ldcg4(&src[i]);
        }
        __syncthreads();

        float acc[8];
#pragma unroll
        for (int q = 0; q < 8; ++q) acc[q] = 0.0f;
        const float4* hb = hs + b;
#pragma unroll 4
        for (int kq = kh * 64; kq < kh * 64 + 64; ++kq) {
            float4 hv = hb[kq * 32];
#pragma unroll
            for (int q = 0; q < 8; ++q) {
                float4 wv = wr4[q * 128 + kq];
                acc[q] += wv.x * hv.x;
                acc[q] += wv.y * hv.y;
                acc[q] += wv.z * hv.z;
                acc[q] += wv.w * hv.w;
            }
        }
#pragma unroll
        for (int q = 0; q < 8; ++q) redA[(w * 8 + q) * 32 + b] = acc[q];
        __syncthreads();

        if (kh == 0) {
            float h2v[2];
#pragma unroll
            for (int u = 0; u < 2; ++u) {
#pragma unroll
                for (int q = 0; q < 4; ++q) {
                    int qq = u * 4 + q;
                    acc[qq] += redA[((w + 4) * 8 + qq) * 32 + b];
                    acc[qq] += pv[qq] + xh * rs[qq];
                }
                float iv = acc[u*4+0], fv = acc[u*4+1], gv = acc[u*4+2], ov = acc[u*4+3];
                cst[u] = fsig(fv) * cst[u] + fsig(iv) * ftanh(gv);
                h2v[u] = fsig(ov) * ftanh(cst[u]);
            }
            stcg2((float2*)&g_H[wbuf][cell][jA >> 2][b][jA & 3],
                  make_float2(h2v[0], h2v[1]));
            if (is_xh) g_XH[sub][t][b] = h2v[1];
        }

        if (step == 2 * Tt - 1) break;
        __syncthreads();
        if (tid == 0) {
            asm volatile("membar.gl;" ::: "memory");
            atomicAdd(&g_bar, 1u);
            unsigned want = (unsigned)(step + 1) * NBLK;
            unsigned v;
            do {
                asm volatile("ld.acquire.gpu.global.u32 %0,[%1];" : "=r"(v) : "l"(&g_bar));
            } while (v < want);
        }
        __syncthreads();
    }
}

// =====================================================================
// Kernel 3: out = 1.5*u + 0.5*(xh1 + xh2)
// =====================================================================
__global__ __launch_bounds__(256) void epi_kernel(const float* __restrict__ U,
                                                  float* __restrict__ out)
{
    int idx = blockIdx.x * blockDim.x + threadIdx.x;
    if (idx >= Bb * Tt * Dd / 4) return;
    int t = (idx >> 7) & (Tt - 1);
    int b = idx >> 17;
    float s = 0.5f * (g_XH[0][t][b] + g_XH[1][t][b]);
    float4 u = ((const float4*)U)[idx];
    ((float4*)out)[idx] = make_float4(1.5f * u.x + s, 1.5f * u.y + s,
                                      1.5f * u.z + s, 1.5f * u.w + s);
}

extern "C" void kernel_launch(void* const* d_in, const int* in_sizes, int n_in,
                              void* d_out, int out_size) {
    const float* U     = (const float*)d_in[0];
    const float* wih_f = (const float*)d_in[1];
    const float* whh_f = (const float*)d_in[2];
    const float* bih_f = (const float*)d_in[3];
    const float* bhh_f = (const float*)d_in[4];
    const float* wih_b = (const float*)d_in[5];
    const float* whh_b = (const float*)d_in[6];
    const float* bih_b = (const float*)d_in[7];
    const float* bhh_b = (const float*)d_in[8];
    float* out = (float*)d_out;

    const int smem_sz = 65536 + 65536 + (8*8*32 + 32 + NTHR) * 4;
    cudaFuncSetAttribute(rec_kernel, cudaFuncAttributeMaxDynamicSharedMemorySize, smem_sz);

    // one-time stream/event creation (host objects only; created on the
    // uncaptured correctness call, reused under capture) — R10-proven pattern.
    static cudaStream_t s2 = nullptr;
    static cudaEvent_t ev_fork = nullptr, ev_join = nullptr;
    if (s2 == nullptr) {
        cudaStreamCreateWithFlags(&s2, cudaStreamNonBlocking);
        cudaEventCreateWithFlags(&ev_fork, cudaEventDisableTiming);
        cudaEventCreateWithFlags(&ev_join, cudaEventDisableTiming);
    }

    void* bar_addr = nullptr;
    void* pcnt_addr = nullptr;
    cudaGetSymbolAddress(&bar_addr, g_bar);
    cudaGetSymbolAddress(&pcnt_addr, g_pcnt);
    cudaMemsetAsync(bar_addr, 0, sizeof(unsigned), 0);
    cudaMemsetAsync(pcnt_addr, 0, Tt * sizeof(unsigned), 0);

    // fork: persistent 148-block producer on s2, rec on default stream.
    cudaEventRecord(ev_fork, 0);
    cudaStreamWaitEvent(s2, ev_fork, 0);
    pre_kernel<<<PREB, 256, 0, s2>>>(U, wih_f, wih_b, bih_f, bhh_f, bih_b, bhh_b);
    cudaEventRecord(ev_join, s2);

    rec_kernel<<<NBLK, NTHR, smem_sz>>>(whh_f, whh_b, wih_f, wih_b);

    // join pre before epilogue
    cudaStreamWaitEvent(0, ev_join, 0);
    epi_kernel<<<(Bb * Tt * Dd / 4 + 255) / 256, 256>>>(U, out);
}

// round 14
// speedup vs baseline: 1.0963x; 1.0963x over previous
#include <cuda_runtime.h>
#include <cstdint>
#include <cstddef>
#include <math.h>

#define Bb 32
#define Tt 1024
#define Dd 512
#define Hh 512
#define R4 4096
#define NBLK 128
#define NTHR 256

__device__ float    g_P[(size_t)Tt * R4 * Bb];   // [t][r][b], r = cell*2048+gate*512+j
__device__ float    g_H[2][2][Hh/4][Bb][4];      // [pp][cell][j/4][b][j&3]
__device__ float    g_XH[2][Tt][Bb];
__device__ unsigned g_bar;

__device__ __forceinline__ float fsig(float x) {
    x = fminf(fmaxf(x, -30.0f), 30.0f);
    return __fdividef(1.0f, 1.0f + __expf(-x));
}
__device__ __forceinline__ float ftanh(float x) {
    x = fminf(fmaxf(x, -15.0f), 15.0f);
    float e = __expf(2.0f * x);
    return __fdividef(e - 1.0f, e + 1.0f);
}
__device__ __forceinline__ float4 ldcg4(const float4* p) {
    float4 v;
    asm volatile("ld.global.cg.v4.f32 {%0,%1,%2,%3},[%4];"
                 : "=f"(v.x), "=f"(v.y), "=f"(v.z), "=f"(v.w) : "l"(p));
    return v;
}
__device__ __forceinline__ void stcg2(float2* p, float2 v) {
    asm volatile("st.global.cg.v2.f32 [%0],{%1,%2};" :: "l"(p), "f"(v.x), "f"(v.y));
}
__device__ __forceinline__ float ldcg1(const float* p) {
    float v; asm volatile("ld.global.cg.f32 %0,[%1];" : "=f"(v) : "l"(p)); return v;
}

// =====================================================================
// Kernel 1: P[t][r][b] = sum_d U[b][t][d]*Wih[r][d] + bih[r] + bhh[r]
// 8x4 register tile (1.5 B LDS per FMA -> FFMA-pipe bound, not crossbar).
// Tile 256 rows x 32 b; grid (16, 1024) x 256 thr.
// =====================================================================
__global__ __launch_bounds__(256) void pre_kernel(
    const float* __restrict__ U,
    const float* __restrict__ wih_f, const float* __restrict__ wih_b,
    const float* __restrict__ bih_f, const float* __restrict__ bhh_f,
    const float* __restrict__ bih_b, const float* __restrict__ bhh_b)
{
    __shared__ float Us[32][36];    // [k][b]
    __shared__ float Ws[32][260];   // [k][row], pad: 4*260 % 32 == 16

    const int t  = blockIdx.y;
    const int r0 = blockIdx.x * 256;
    const int cb = (r0 >= 2048);
    const float* wih = cb ? wih_b : wih_f;
    const int rbase = r0 - cb * 2048;

    const int tid = threadIdx.x;
    const int b0  = (tid & 7) * 4;
    const int rr0 = (tid >> 3) * 8;        // 8 rows per thread
    const int bb  = tid >> 3;              // U row for staging
    const int kq  = tid & 7;               // k-quad for staging

    float acc[8][4];
#pragma unroll
    for (int i = 0; i < 8; ++i)
#pragma unroll
        for (int j = 0; j < 4; ++j) acc[i][j] = 0.0f;

    for (int kt = 0; kt < 16; ++kt) {
        const int k0 = kt * 32;
        {   // U tile: 32 b x 32 k -> Us[k][b]
            float4 v = *(const float4*)&U[(size_t)bb * (Tt * Dd) + (size_t)t * Dd + k0 + kq * 4];
            Us[kq * 4 + 0][bb] = v.x; Us[kq * 4 + 1][bb] = v.y;
            Us[kq * 4 + 2][bb] = v.z; Us[kq * 4 + 3][bb] = v.w;
        }
#pragma unroll
        for (int ii = 0; ii < 8; ++ii) {   // W tile: 256 r x 32 k -> Ws[k][r]
            int rr = (tid >> 3) + 32 * ii;
            float4 v = *(const float4*)&wih[(size_t)(rbase + rr) * Dd + k0 + kq * 4];
            Ws[kq * 4 + 0][rr] = v.x; Ws[kq * 4 + 1][rr] = v.y;
            Ws[kq * 4 + 2][rr] = v.z; Ws[kq * 4 + 3][rr] = v.w;
        }
        __syncthreads();
#pragma unroll
        for (int k = 0; k < 32; ++k) {
            float4 ub = *(const float4*)&Us[k][b0];
            float4 wA = *(const float4*)&Ws[k][rr0];
            float4 wB = *(const float4*)&Ws[k][rr0 + 4];
            acc[0][0] += wA.x*ub.x; acc[0][1] += wA.x*ub.y; acc[0][2] += wA.x*ub.z; acc[0][3] += wA.x*ub.w;
            acc[1][0] += wA.y*ub.x; acc[1][1] += wA.y*ub.y; acc[1][2] += wA.y*ub.z; acc[1][3] += wA.y*ub.w;
            acc[2][0] += wA.z*ub.x; acc[2][1] += wA.z*ub.y; acc[2][2] += wA.z*ub.z; acc[2][3] += wA.z*ub.w;
            acc[3][0] += wA.w*ub.x; acc[3][1] += wA.w*ub.y; acc[3][2] += wA.w*ub.z; acc[3][3] += wA.w*ub.w;
            acc[4][0] += wB.x*ub.x; acc[4][1] += wB.x*ub.y; acc[4][2] += wB.x*ub.z; acc[4][3] += wB.x*ub.w;
            acc[5][0] += wB.y*ub.x; acc[5][1] += wB.y*ub.y; acc[5][2] += wB.y*ub.z; acc[5][3] += wB.y*ub.w;
            acc[6][0] += wB.z*ub.x; acc[6][1] += wB.z*ub.y; acc[6][2] += wB.z*ub.z; acc[6][3] += wB.z*ub.w;
            acc[7][0] += wB.w*ub.x; acc[7][1] += wB.w*ub.y; acc[7][2] += wB.w*ub.z; acc[7][3] += wB.w*ub.w;
        }
        __syncthreads();
    }
#pragma unroll
    for (int i = 0; i < 8; ++i) {
        int rw = rbase + rr0 + i;
        float bias = cb ? (bih_b[rw] + bhh_b[rw]) : (bih_f[rw] + bhh_f[rw]);
        float4 o = make_float4(acc[i][0]+bias, acc[i][1]+bias, acc[i][2]+bias, acc[i][3]+bias);
        *(float4*)&g_P[((size_t)t * R4 + (size_t)(r0 + rr0 + i)) * Bb + b0] = o;
    }
}

// =====================================================================
// Kernel 2: persistent recurrence (proven best version — unchanged).
// =====================================================================
__global__ void __launch_bounds__(NTHR, 1) rec_kernel(
    const float* __restrict__ whh_f, const float* __restrict__ whh_b,
    const float* __restrict__ wih_f, const float* __restrict__ wih_b)
{
    extern __shared__ char smraw[];
    float*  ws   = (float*)smraw;                 // [32 rows][512]  row = p*8+u*4+gate
    float4* hs   = (float4*)(smraw + 65536);      // [128 kq][32 b]
    float*  redA = (float*)(smraw + 131072);      // [8 w][8 q][32 b]
    float*  rsum = redA + 8*8*32;                 // [32]
    float*  red  = rsum + 32;                     // [256]

    const int tid  = threadIdx.x;
    const int w    = tid >> 5;
    const int p    = w & 3;
    const int kh   = w >> 2;
    const int b    = tid & 31;
    const int cell = blockIdx.x >> 6;
    const int g    = blockIdx.x & 63;
    const int jA   = g * 8 + 2 * p;

    const float* whh = cell ? whh_b : whh_f;
    const float* wih = cell ? wih_b : wih_f;

    for (int idx = tid * 4; idx < 32 * 512; idx += NTHR * 4) {
        int rl = idx >> 9, k = idx & 511;
        int p_ = rl >> 3, q = rl & 7, u = q >> 2, gate = q & 3;
        int grow = gate * 512 + g * 8 + 2 * p_ + u;
        *(float4*)&ws[idx] = *(const float4*)&whh[(size_t)grow * 512 + k];
    }
    {   // rowsums of Wih (sub-step-2 scalar-broadcast projection)
        int rl = tid & 31, part = tid >> 5;
        int p_ = rl >> 3, q = rl & 7, u = q >> 2, gate = q & 3;
        int grow = gate * 512 + g * 8 + 2 * p_ + u;
        float s = 0.0f;
        const float* pp = &wih[(size_t)grow * 512 + part * 64];
#pragma unroll 4
        for (int k = 0; k < 64; k += 4) {
            float4 v = *(const float4*)&pp[k];
            s += v.x + v.y + v.z + v.w;
        }
        red[tid] = s;
    }
    __syncthreads();
    if (tid < 32) {
        float s = 0.0f;
#pragma unroll
        for (int q = 0; q < 8; ++q) s += red[tid + 32 * q];
        rsum[tid] = s;
    }
    __syncthreads();
    float rs[8];
#pragma unroll
    for (int q = 0; q < 8; ++q) rs[q] = rsum[p * 8 + q];

    float cst[2] = {0.0f, 0.0f};
    const float4* wr4 = (const float4*)(ws + (p * 8) * 512);
    const bool is_xh = (cell == 1 && jA + 1 == Hh - 1);

    for (int step = 0; step < 2 * Tt; ++step) {
        const int t = step >> 1, sub = step & 1;
        const int rbuf = step & 1, wbuf = rbuf ^ 1;

        float pv[8];
        if (kh == 0) {
            const float* Pt = g_P + ((size_t)t * R4 + (size_t)cell * 2048) * Bb;
#pragma unroll
            for (int q = 0; q < 8; ++q) {
                int u = q >> 2, gate = q & 3;
                pv[q] = ldcg1(&Pt[(size_t)(gate * 512 + jA + u) * Bb + b]);
            }
        }
        float xh = (sub && kh == 0) ? ldcg1(&g_H[rbuf][1][(Hh - 1) >> 2][b][3]) : 0.0f;

        if (step == 0) {
            float4 z = make_float4(0.f, 0.f, 0.f, 0.f);
            for (int i = tid; i < 128 * 32; i += NTHR) hs[i] = z;
        } else {
            const float4* src = (const float4*)&g_H[rbuf][cell][0][0][0];
            for (int i = tid; i < 128 * 32; i += NTHR) hs[i] = ldcg4(&src[i]);
        }
        __syncthreads();

        float acc[8];
#pragma unroll
        for (int q = 0; q < 8; ++q) acc[q] = 0.0f;
        const float4* hb = hs + b;
#pragma unroll 4
        for (int kq = kh * 64; kq < kh * 64 + 64; ++kq) {
            float4 hv = hb[kq * 32];
#pragma unroll
            for (int q = 0; q < 8; ++q) {
                float4 wv = wr4[q * 128 + kq];
                acc[q] += wv.x * hv.x;
                acc[q] += wv.y * hv.y;
                acc[q] += wv.z * hv.z;
                acc[q] += wv.w * hv.w;
            }
        }
#pragma unroll
        for (int q = 0; q < 8; ++q) redA[(w * 8 + q) * 32 + b] = acc[q];
        __syncthreads();

        if (kh == 0) {
            float h2v[2];
#pragma unroll
            for (int u = 0; u < 2; ++u) {
#pragma unroll
                for (int q = 0; q < 4; ++q) {
                    int qq = u * 4 + q;
                    acc[qq] += redA[((w + 4) * 8 + qq) * 32 + b];
                    acc[qq] += pv[qq] + xh * rs[qq];
                }
                float iv = acc[u*4+0], fv = acc[u*4+1], gv = acc[u*4+2], ov = acc[u*4+3];
                cst[u] = fsig(fv) * cst[u] + fsig(iv) * ftanh(gv);
                h2v[u] = fsig(ov) * ftanh(cst[u]);
            }
            stcg2((float2*)&g_H[wbuf][cell][jA >> 2][b][jA & 3],
                  make_float2(h2v[0], h2v[1]));
            if (is_xh) g_XH[sub][t][b] = h2v[1];
        }

        if (step == 2 * Tt - 1) break;
        __syncthreads();
        if (tid == 0) {
            asm volatile("membar.gl;" ::: "memory");
            atomicAdd(&g_bar, 1u);
            unsigned want = (unsigned)(step + 1) * NBLK;
            unsigned v;
            do {
                asm volatile("ld.acquire.gpu.global.u32 %0,[%1];" : "=r"(v) : "l"(&g_bar));
            } while (v < want);
        }
        __syncthreads();
    }
}

// =====================================================================
// Kernel 3: out = 1.5*u + 0.5*(xh1 + xh2)
// =====================================================================
__global__ __launch_bounds__(256) void epi_kernel(const float* __restrict__ U,
                                                  float* __restrict__ out)
{
    int idx = blockIdx.x * blockDim.x + threadIdx.x;
    if (idx >= Bb * Tt * Dd / 4) return;
    int t = (idx >> 7) & (Tt - 1);
    int b = idx >> 17;
    float s = 0.5f * (g_XH[0][t][b] + g_XH[1][t][b]);
    float4 u = ((const float4*)U)[idx];
    ((float4*)out)[idx] = make_float4(1.5f * u.x + s, 1.5f * u.y + s,
                                      1.5f * u.z + s, 1.5f * u.w + s);
}

extern "C" void kernel_launch(void* const* d_in, const int* in_sizes, int n_in,
                              void* d_out, int out_size) {
    const float* U     = (const float*)d_in[0];
    const float* wih_f = (const float*)d_in[1];
    const float* whh_f = (const float*)d_in[2];
    const float* bih_f = (const float*)d_in[3];
    const float* bhh_f = (const float*)d_in[4];
    const float* wih_b = (const float*)d_in[5];
    const float* whh_b = (const float*)d_in[6];
    const float* bih_b = (const float*)d_in[7];
    const float* bhh_b = (const float*)d_in[8];
    float* out = (float*)d_out;

    const int smem_sz = 65536 + 65536 + (8*8*32 + 32 + NTHR) * 4;
    cudaFuncSetAttribute(rec_kernel, cudaFuncAttributeMaxDynamicSharedMemorySize, smem_sz);

    void* bar_addr = nullptr;
    cudaGetSymbolAddress(&bar_addr, g_bar);
    cudaMemsetAsync(bar_addr, 0, sizeof(unsigned), 0);

    pre_kernel<<<dim3(16, Tt), 256>>>(U, wih_f, wih_b, bih_f, bhh_f, bih_b, bhh_b);
    rec_kernel<<<NBLK, NTHR, smem_sz>>>(whh_f, whh_b, wih_f, wih_b);
    epi_kernel<<<(Bb * Tt * Dd / 4 + 255) / 256, 256>>>(U, out);
}

// round 16
// speedup vs baseline: 1.1128x; 1.0151x over previous
#include <cuda_runtime.h>
#include <cstdint>
#include <cstddef>
#include <math.h>

#define Bb 32
#define Tt 1024
#define Dd 512
#define Hh 512
#define R4 4096
#define NBLK 128
#define NTHR 256

__device__ float    g_P[(size_t)Tt * R4 * Bb];   // [t][r][b], r = cell*2048+gate*512+j
__device__ float    g_H[2][2][Hh/4][Bb][4];      // [pp][cell][j/4][b][j&3]
__device__ float    g_XH[2][Tt][Bb];
__device__ unsigned g_bar2[2];                   // per-cell barrier counters
__device__ unsigned g_xbar;                      // xh publication counter (block 127)

__device__ __forceinline__ float fsig(float x) {
    x = fminf(fmaxf(x, -30.0f), 30.0f);
    return __fdividef(1.0f, 1.0f + __expf(-x));
}
__device__ __forceinline__ float ftanh(float x) {
    x = fminf(fmaxf(x, -15.0f), 15.0f);
    float e = __expf(2.0f * x);
    return __fdividef(e - 1.0f, e + 1.0f);
}
__device__ __forceinline__ float4 ldcg4(const float4* p) {
    float4 v;
    asm volatile("ld.global.cg.v4.f32 {%0,%1,%2,%3},[%4];"
                 : "=f"(v.x), "=f"(v.y), "=f"(v.z), "=f"(v.w) : "l"(p));
    return v;
}
__device__ __forceinline__ void stcg2(float2* p, float2 v) {
    asm volatile("st.global.cg.v2.f32 [%0],{%1,%2};" :: "l"(p), "f"(v.x), "f"(v.y));
}
__device__ __forceinline__ float ldcg1(const float* p) {
    float v; asm volatile("ld.global.cg.f32 %0,[%1];" : "=f"(v) : "l"(p)); return v;
}
__device__ __forceinline__ unsigned ldacq(const unsigned* p) {
    unsigned v;
    asm volatile("ld.acquire.gpu.global.u32 %0,[%1];" : "=r"(v) : "l"(p));
    return v;
}

// =====================================================================
// Kernel 1: P[t][r][b] = sum_d U[b][t][d]*Wih[r][d] + bih[r] + bhh[r]
// R6 proven-best config: 4x4 tile, double-buffered K-tiles.
// =====================================================================
__global__ __launch_bounds__(256) void pre_kernel(
    const float* __restrict__ U,
    const float* __restrict__ wih_f, const float* __restrict__ wih_b,
    const float* __restrict__ bih_f, const float* __restrict__ bhh_f,
    const float* __restrict__ bih_b, const float* __restrict__ bhh_b)
{
    __shared__ float Us[2][32][36];
    __shared__ float Ws[2][32][132];

    const int t  = blockIdx.y;
    const int r0 = blockIdx.x * 128;
    const int cb = (r0 >= 2048);
    const float* wih = cb ? wih_b : wih_f;
    const int rbase = r0 - cb * 2048;

    const int tid = threadIdx.x;
    const int b0  = (tid & 7) * 4;
    const int rr0 = ((tid >> 3) & 31) * 4;
    const int bb  = tid >> 3;
    const int kq  = tid & 7;

    const float* Ubase = &U[(size_t)bb * (Tt * Dd) + (size_t)t * Dd + kq * 4];
    const float* Wbase = &wih[(size_t)(rbase + (tid >> 3)) * Dd + kq * 4];

    float acc[4][4];
#pragma unroll
    for (int i = 0; i < 4; ++i)
#pragma unroll
        for (int j = 0; j < 4; ++j) acc[i][j] = 0.0f;

    float4 pu  = *(const float4*)Ubase;
    float4 pw0 = *(const float4*)&Wbase[(size_t)(32 * 0) * Dd];
    float4 pw1 = *(const float4*)&Wbase[(size_t)(32 * 1) * Dd];
    float4 pw2 = *(const float4*)&Wbase[(size_t)(32 * 2) * Dd];
    float4 pw3 = *(const float4*)&Wbase[(size_t)(32 * 3) * Dd];
    {
        Us[0][kq*4+0][bb] = pu.x; Us[0][kq*4+1][bb] = pu.y;
        Us[0][kq*4+2][bb] = pu.z; Us[0][kq*4+3][bb] = pu.w;
        int rr = tid >> 3;
        Ws[0][kq*4+0][rr+ 0] = pw0.x; Ws[0][kq*4+1][rr+ 0] = pw0.y;
        Ws[0][kq*4+2][rr+ 0] = pw0.z; Ws[0][kq*4+3][rr+ 0] = pw0.w;
        Ws[0][kq*4+0][rr+32] = pw1.x; Ws[0][kq*4+1][rr+32] = pw1.y;
        Ws[0][kq*4+2][rr+32] = pw1.z; Ws[0][kq*4+3][rr+32] = pw1.w;
        Ws[0][kq*4+0][rr+64] = pw2.x; Ws[0][kq*4+1][rr+64] = pw2.y;
        Ws[0][kq*4+2][rr+64] = pw2.z; Ws[0][kq*4+3][rr+64] = pw2.w;
        Ws[0][kq*4+0][rr+96] = pw3.x; Ws[0][kq*4+1][rr+96] = pw3.y;
        Ws[0][kq*4+2][rr+96] = pw3.z; Ws[0][kq*4+3][rr+96] = pw3.w;
    }
    __syncthreads();

    for (int kt = 0; kt < 16; ++kt) {
        const int cur = kt & 1;
        if (kt < 15) {
            const int k1 = (kt + 1) * 32;
            pu  = *(const float4*)&Ubase[k1];
            pw0 = *(const float4*)&Wbase[(size_t)(32 * 0) * Dd + k1];
            pw1 = *(const float4*)&Wbase[(size_t)(32 * 1) * Dd + k1];
            pw2 = *(const float4*)&Wbase[(size_t)(32 * 2) * Dd + k1];
            pw3 = *(const float4*)&Wbase[(size_t)(32 * 3) * Dd + k1];
        }
#pragma unroll
        for (int k = 0; k < 32; ++k) {
            float4 ub = *(const float4*)&Us[cur][k][b0];
            float4 wr = *(const float4*)&Ws[cur][k][rr0];
            acc[0][0] += wr.x*ub.x; acc[0][1] += wr.x*ub.y; acc[0][2] += wr.x*ub.z; acc[0][3] += wr.x*ub.w;
            acc[1][0] += wr.y*ub.x; acc[1][1] += wr.y*ub.y; acc[1][2] += wr.y*ub.z; acc[1][3] += wr.y*ub.w;
            acc[2][0] += wr.z*ub.x; acc[2][1] += wr.z*ub.y; acc[2][2] += wr.z*ub.z; acc[2][3] += wr.z*ub.w;
            acc[3][0] += wr.w*ub.x; acc[3][1] += wr.w*ub.y; acc[3][2] += wr.w*ub.z; acc[3][3] += wr.w*ub.w;
        }
        if (kt < 15) {
            const int nxt = cur ^ 1;
            Us[nxt][kq*4+0][bb] = pu.x; Us[nxt][kq*4+1][bb] = pu.y;
            Us[nxt][kq*4+2][bb] = pu.z; Us[nxt][kq*4+3][bb] = pu.w;
            int rr = tid >> 3;
            Ws[nxt][kq*4+0][rr+ 0] = pw0.x; Ws[nxt][kq*4+1][rr+ 0] = pw0.y;
            Ws[nxt][kq*4+2][rr+ 0] = pw0.z; Ws[nxt][kq*4+3][rr+ 0] = pw0.w;
            Ws[nxt][kq*4+0][rr+32] = pw1.x; Ws[nxt][kq*4+1][rr+32] = pw1.y;
            Ws[nxt][kq*4+2][rr+32] = pw1.z; Ws[nxt][kq*4+3][rr+32] = pw1.w;
            Ws[nxt][kq*4+0][rr+64] = pw2.x; Ws[nxt][kq*4+1][rr+64] = pw2.y;
            Ws[nxt][kq*4+2][rr+64] = pw2.z; Ws[nxt][kq*4+3][rr+64] = pw2.w;
            Ws[nxt][kq*4+0][rr+96] = pw3.x; Ws[nxt][kq*4+1][rr+96] = pw3.y;
            Ws[nxt][kq*4+2][rr+96] = pw3.z; Ws[nxt][kq*4+3][rr+96] = pw3.w;
            __syncthreads();
        }
    }
#pragma unroll
    for (int i = 0; i < 4; ++i) {
        int rw = rbase + rr0 + i;
        float bias = cb ? (bih_b[rw] + bhh_b[rw]) : (bih_f[rw] + bhh_f[rw]);
        float4 o = make_float4(acc[i][0]+bias, acc[i][1]+bias, acc[i][2]+bias, acc[i][3]+bias);
        *(float4*)&g_P[((size_t)t * R4 + (size_t)(r0 + rr0 + i)) * Bb + b0] = o;
    }
}

// =====================================================================
// Kernel 2: persistent recurrence with PER-CELL barriers (64 arrivals)
// + xh flag waited on post-matvec (zero exposed latency steady-state).
// =====================================================================
__global__ void __launch_bounds__(NTHR, 1) rec_kernel(
    const float* __restrict__ whh_f, const float* __restrict__ whh_b,
    const float* __restrict__ wih_f, const float* __restrict__ wih_b)
{
    extern __shared__ char smraw[];
    float*  ws   = (float*)smraw;                 // [32 rows][512]  row = p*8+u*4+gate
    float4* hs   = (float4*)(smraw + 65536);      // [128 kq][32 b]
    float*  redA = (float*)(smraw + 131072);      // [8 w][8 q][32 b]
    float*  rsum = redA + 8*8*32;                 // [32]
    float*  red  = rsum + 32;                     // [256]

    const int tid  = threadIdx.x;
    const int w    = tid >> 5;
    const int p    = w & 3;
    const int kh   = w >> 2;
    const int b    = tid & 31;
    const int cell = blockIdx.x >> 6;
    const int g    = blockIdx.x & 63;
    const int jA   = g * 8 + 2 * p;

    const float* whh = cell ? whh_b : whh_f;
    const float* wih = cell ? wih_b : wih_f;

    for (int idx = tid * 4; idx < 32 * 512; idx += NTHR * 4) {
        int rl = idx >> 9, k = idx & 511;
        int p_ = rl >> 3, q = rl & 7, u = q >> 2, gate = q & 3;
        int grow = gate * 512 + g * 8 + 2 * p_ + u;
        *(float4*)&ws[idx] = *(const float4*)&whh[(size_t)grow * 512 + k];
    }
    {   // rowsums of Wih (sub-step-2 scalar-broadcast projection)
        int rl = tid & 31, part = tid >> 5;
        int p_ = rl >> 3, q = rl & 7, u = q >> 2, gate = q & 3;
        int grow = gate * 512 + g * 8 + 2 * p_ + u;
        float s = 0.0f;
        const float* pp = &wih[(size_t)grow * 512 + part * 64];
#pragma unroll 4
        for (int k = 0; k < 64; k += 4) {
            float4 v = *(const float4*)&pp[k];
            s += v.x + v.y + v.z + v.w;
        }
        red[tid] = s;
    }
    __syncthreads();
    if (tid < 32) {
        float s = 0.0f;
#pragma unroll
        for (int q = 0; q < 8; ++q) s += red[tid + 32 * q];
        rsum[tid] = s;
    }
    __syncthreads();
    float rs[8];
#pragma unroll
    for (int q = 0; q < 8; ++q) rs[q] = rsum[p * 8 + q];

    float cst[2] = {0.0f, 0.0f};
    const float4* wr4 = (const float4*)(ws + (p * 8) * 512);
    const bool is_xh       = (cell == 1 && jA + 1 == Hh - 1);   // thread-row owns unit 511
    const bool is_xh_block = (cell == 1 && g == 63);            // block 127 publishes xh flag

    for (int step = 0; step < 2 * Tt; ++step) {
        const int t = step >> 1, sub = step & 1;
        const int rbuf = step & 1, wbuf = rbuf ^ 1;

        float pv[8];
        if (kh == 0) {
            const float* Pt = g_P + ((size_t)t * R4 + (size_t)cell * 2048) * Bb;
#pragma unroll
            for (int q = 0; q < 8; ++q) {
                int u = q >> 2, gate = q & 3;
                pv[q] = ldcg1(&Pt[(size_t)(gate * 512 + jA + u) * Bb + b]);
            }
        }

        if (step == 0) {
            float4 z = make_float4(0.f, 0.f, 0.f, 0.f);
            for (int i = tid; i < 128 * 32; i += NTHR) hs[i] = z;
        } else {
            const float4* src = (const float4*)&g_H[rbuf][cell][0][0][0];
            for (int i = tid; i < 128 * 32; i += NTHR) hs[i] = ldcg4(&src[i]);
        }
        __syncthreads();

        float acc[8];
#pragma unroll
        for (int q = 0; q < 8; ++q) acc[q] = 0.0f;
        const float4* hb = hs + b;
#pragma unroll 4
        for (int kq = kh * 64; kq < kh * 64 + 64; ++kq) {
            float4 hv = hb[kq * 32];
#pragma unroll
            for (int q = 0; q < 8; ++q) {
                float4 wv = wr4[q * 128 + kq];
                acc[q] += wv.x * hv.x;
                acc[q] += wv.y * hv.y;
                acc[q] += wv.z * hv.z;
                acc[q] += wv.w * hv.w;
            }
        }
#pragma unroll
        for (int q = 0; q < 8; ++q) redA[(w * 8 + q) * 32 + b] = acc[q];
        __syncthreads();

        if (kh == 0) {
            // xh: published by block 127 at end of step-1; steady-state the
            // flag is already set -> single L2 load, no stall.
            float xh = 0.0f;
            if (sub) {
                while (ldacq(&g_xbar) < (unsigned)step) { }
                xh = ldcg1(&g_H[rbuf][1][(Hh - 1) >> 2][b][3]);
            }
            float h2v[2];
#pragma unroll
            for (int u = 0; u < 2; ++u) {
#pragma unroll
                for (int q = 0; q < 4; ++q) {
                    int qq = u * 4 + q;
                    acc[qq] += redA[((w + 4) * 8 + qq) * 32 + b];
                    acc[qq] += pv[qq] + xh * rs[qq];
                }
                float iv = acc[u*4+0], fv = acc[u*4+1], gv = acc[u*4+2], ov = acc[u*4+3];
                cst[u] = fsig(fv) * cst[u] + fsig(iv) * ftanh(gv);
                h2v[u] = fsig(ov) * ftanh(cst[u]);
            }
            stcg2((float2*)&g_H[wbuf][cell][jA >> 2][b][jA & 3],
                  make_float2(h2v[0], h2v[1]));
            if (is_xh) g_XH[sub][t][b] = h2v[1];
        }

        if (step == 2 * Tt - 1) break;
        __syncthreads();
        if (tid == 0) {
            asm volatile("membar.gl;" ::: "memory");
            if (is_xh_block) atomicAdd(&g_xbar, 1u);     // publish xh of this step
            atomicAdd(&g_bar2[cell], 1u);
            unsigned want = (unsigned)(step + 1) * 64u;
            while (ldacq(&g_bar2[cell]) < want) { }
        }
        __syncthreads();
    }
}

// =====================================================================
// Kernel 3: out = 1.5*u + 0.5*(xh1 + xh2)
// =====================================================================
__global__ __launch_bounds__(256) void epi_kernel(const float* __restrict__ U,
                                                  float* __restrict__ out)
{
    int idx = blockIdx.x * blockDim.x + threadIdx.x;
    if (idx >= Bb * Tt * Dd / 4) return;
    int t = (idx >> 7) & (Tt - 1);
    int b = idx >> 17;
    float s = 0.5f * (g_XH[0][t][b] + g_XH[1][t][b]);
    float4 u = ((const float4*)U)[idx];
    ((float4*)out)[idx] = make_float4(1.5f * u.x + s, 1.5f * u.y + s,
                                      1.5f * u.z + s, 1.5f * u.w + s);
}

extern "C" void kernel_launch(void* const* d_in, const int* in_sizes, int n_in,
                              void* d_out, int out_size) {
    const float* U     = (const float*)d_in[0];
    const float* wih_f = (const float*)d_in[1];
    const float* whh_f = (const float*)d_in[2];
    const float* bih_f = (const float*)d_in[3];
    const float* bhh_f = (const float*)d_in[4];
    const float* wih_b = (const float*)d_in[5];
    const float* whh_b = (const float*)d_in[6];
    const float* bih_b = (const float*)d_in[7];
    const float* bhh_b = (const float*)d_in[8];
    float* out = (float*)d_out;

    const int smem_sz = 65536 + 65536 + (8*8*32 + 32 + NTHR) * 4;
    cudaFuncSetAttribute(rec_kernel, cudaFuncAttributeMaxDynamicSharedMemorySize, smem_sz);

    void* bar2_addr = nullptr;
    void* xbar_addr = nullptr;
    cudaGetSymbolAddress(&bar2_addr, g_bar2);
    cudaGetSymbolAddress(&xbar_addr, g_xbar);
    cudaMemsetAsync(bar2_addr, 0, 2 * sizeof(unsigned), 0);
    cudaMemsetAsync(xbar_addr, 0, sizeof(unsigned), 0);

    pre_kernel<<<dim3(32, Tt), 256>>>(U, wih_f, wih_b, bih_f, bhh_f, bih_b, bhh_b);
    rec_kernel<<<NBLK, NTHR, smem_sz>>>(whh_f, whh_b, wih_f, wih_b);
    epi_kernel<<<(Bb * Tt * Dd / 4 + 255) / 256, 256>>>(U, out);
}

// round 17
// speedup vs baseline: 1.1188x; 1.0054x over previous
#include <cuda_runtime.h>
#include <cstdint>
#include <cstddef>
#include <math.h>

#define Bb 32
#define Tt 1024
#define Dd 512
#define Hh 512
#define R4 4096
#define NBLK 128
#define NTHR 256

typedef unsigned long long u64;

__device__ float    g_P[(size_t)Tt * R4 * Bb];   // [t][r][b], r = cell*2048+gate*512+j
__device__ float    g_H[2][2][Hh/4][Bb][4];      // [pp][cell][j/4][b][j&3]
__device__ float    g_XH[2][Tt][Bb];
__device__ unsigned g_bar;

__device__ __forceinline__ float fsig(float x) {
    x = fminf(fmaxf(x, -30.0f), 30.0f);
    return __fdividef(1.0f, 1.0f + __expf(-x));
}
__device__ __forceinline__ float ftanh(float x) {
    x = fminf(fmaxf(x, -15.0f), 15.0f);
    float e = __expf(2.0f * x);
    return __fdividef(e - 1.0f, e + 1.0f);
}
__device__ __forceinline__ float4 ldcg4(const float4* p) {
    float4 v;
    asm volatile("ld.global.cg.v4.f32 {%0,%1,%2,%3},[%4];"
                 : "=f"(v.x), "=f"(v.y), "=f"(v.z), "=f"(v.w) : "l"(p));
    return v;
}
__device__ __forceinline__ void stcg2(float2* p, float2 v) {
    asm volatile("st.global.cg.v2.f32 [%0],{%1,%2};" :: "l"(p), "f"(v.x), "f"(v.y));
}
__device__ __forceinline__ float ldcg1(const float* p) {
    float v; asm volatile("ld.global.cg.f32 %0,[%1];" : "=f"(v) : "l"(p)); return v;
}
__device__ __forceinline__ void fma2(u64& d, u64 a, u64 b) {
    asm("fma.rn.f32x2 %0,%1,%2,%0;" : "+l"(d) : "l"(a), "l"(b));
}
union F4U2 { float4 f4; u64 u2[2]; };

// =====================================================================
// Kernel 1: P[t][r][b] = sum_d U[b][t][d]*Wih[r][d] + bih[r] + bhh[r]
// (R6 proven config — unchanged)
// =====================================================================
__global__ __launch_bounds__(256) void pre_kernel(
    const float* __restrict__ U,
    const float* __restrict__ wih_f, const float* __restrict__ wih_b,
    const float* __restrict__ bih_f, const float* __restrict__ bhh_f,
    const float* __restrict__ bih_b, const float* __restrict__ bhh_b)
{
    __shared__ float Us[2][32][36];
    __shared__ float Ws[2][32][132];

    const int t  = blockIdx.y;
    const int r0 = blockIdx.x * 128;
    const int cb = (r0 >= 2048);
    const float* wih = cb ? wih_b : wih_f;
    const int rbase = r0 - cb * 2048;

    const int tid = threadIdx.x;
    const int b0  = (tid & 7) * 4;
    const int rr0 = ((tid >> 3) & 31) * 4;
    const int bb  = tid >> 3;
    const int kq  = tid & 7;

    const float* Ubase = &U[(size_t)bb * (Tt * Dd) + (size_t)t * Dd + kq * 4];
    const float* Wbase = &wih[(size_t)(rbase + (tid >> 3)) * Dd + kq * 4];

    float acc[4][4];
#pragma unroll
    for (int i = 0; i < 4; ++i)
#pragma unroll
        for (int j = 0; j < 4; ++j) acc[i][j] = 0.0f;

    float4 pu  = *(const float4*)Ubase;
    float4 pw0 = *(const float4*)&Wbase[(size_t)(32 * 0) * Dd];
    float4 pw1 = *(const float4*)&Wbase[(size_t)(32 * 1) * Dd];
    float4 pw2 = *(const float4*)&Wbase[(size_t)(32 * 2) * Dd];
    float4 pw3 = *(const float4*)&Wbase[(size_t)(32 * 3) * Dd];
    {
        Us[0][kq*4+0][bb] = pu.x; Us[0][kq*4+1][bb] = pu.y;
        Us[0][kq*4+2][bb] = pu.z; Us[0][kq*4+3][bb] = pu.w;
        int rr = tid >> 3;
        Ws[0][kq*4+0][rr+ 0] = pw0.x; Ws[0][kq*4+1][rr+ 0] = pw0.y;
        Ws[0][kq*4+2][rr+ 0] = pw0.z; Ws[0][kq*4+3][rr+ 0] = pw0.w;
        Ws[0][kq*4+0][rr+32] = pw1.x; Ws[0][kq*4+1][rr+32] = pw1.y;
        Ws[0][kq*4+2][rr+32] = pw1.z; Ws[0][kq*4+3][rr+32] = pw1.w;
        Ws[0][kq*4+0][rr+64] = pw2.x; Ws[0][kq*4+1][rr+64] = pw2.y;
        Ws[0][kq*4+2][rr+64] = pw2.z; Ws[0][kq*4+3][rr+64] = pw2.w;
        Ws[0][kq*4+0][rr+96] = pw3.x; Ws[0][kq*4+1][rr+96] = pw3.y;
        Ws[0][kq*4+2][rr+96] = pw3.z; Ws[0][kq*4+3][rr+96] = pw3.w;
    }
    __syncthreads();

    for (int kt = 0; kt < 16; ++kt) {
        const int cur = kt & 1;
        if (kt < 15) {
            const int k1 = (kt + 1) * 32;
            pu  = *(const float4*)&Ubase[k1];
            pw0 = *(const float4*)&Wbase[(size_t)(32 * 0) * Dd + k1];
            pw1 = *(const float4*)&Wbase[(size_t)(32 * 1) * Dd + k1];
            pw2 = *(const float4*)&Wbase[(size_t)(32 * 2) * Dd + k1];
            pw3 = *(const float4*)&Wbase[(size_t)(32 * 3) * Dd + k1];
        }
#pragma unroll
        for (int k = 0; k < 32; ++k) {
            float4 ub = *(const float4*)&Us[cur][k][b0];
            float4 wr = *(const float4*)&Ws[cur][k][rr0];
            acc[0][0] += wr.x*ub.x; acc[0][1] += wr.x*ub.y; acc[0][2] += wr.x*ub.z; acc[0][3] += wr.x*ub.w;
            acc[1][0] += wr.y*ub.x; acc[1][1] += wr.y*ub.y; acc[1][2] += wr.y*ub.z; acc[1][3] += wr.y*ub.w;
            acc[2][0] += wr.z*ub.x; acc[2][1] += wr.z*ub.y; acc[2][2] += wr.z*ub.z; acc[2][3] += wr.z*ub.w;
            acc[3][0] += wr.w*ub.x; acc[3][1] += wr.w*ub.y; acc[3][2] += wr.w*ub.z; acc[3][3] += wr.w*ub.w;
        }
        if (kt < 15) {
            const int nxt = cur ^ 1;
            Us[nxt][kq*4+0][bb] = pu.x; Us[nxt][kq*4+1][bb] = pu.y;
            Us[nxt][kq*4+2][bb] = pu.z; Us[nxt][kq*4+3][bb] = pu.w;
            int rr = tid >> 3;
            Ws[nxt][kq*4+0][rr+ 0] = pw0.x; Ws[nxt][kq*4+1][rr+ 0] = pw0.y;
            Ws[nxt][kq*4+2][rr+ 0] = pw0.z; Ws[nxt][kq*4+3][rr+ 0] = pw0.w;
            Ws[nxt][kq*4+0][rr+32] = pw1.x; Ws[nxt][kq*4+1][rr+32] = pw1.y;
            Ws[nxt][kq*4+2][rr+32] = pw1.z; Ws[nxt][kq*4+3][rr+32] = pw1.w;
            Ws[nxt][kq*4+0][rr+64] = pw2.x; Ws[nxt][kq*4+1][rr+64] = pw2.y;
            Ws[nxt][kq*4+2][rr+64] = pw2.z; Ws[nxt][kq*4+3][rr+64] = pw2.w;
            Ws[nxt][kq*4+0][rr+96] = pw3.x; Ws[nxt][kq*4+1][rr+96] = pw3.y;
            Ws[nxt][kq*4+2][rr+96] = pw3.z; Ws[nxt][kq*4+3][rr+96] = pw3.w;
            __syncthreads();
        }
    }
#pragma unroll
    for (int i = 0; i < 4; ++i) {
        int rw = rbase + rr0 + i;
        float bias = cb ? (bih_b[rw] + bhh_b[rw]) : (bih_f[rw] + bhh_f[rw]);
        float4 o = make_float4(acc[i][0]+bias, acc[i][1]+bias, acc[i][2]+bias, acc[i][3]+bias);
        *(float4*)&g_P[((size_t)t * R4 + (size_t)(r0 + rr0 + i)) * Bb + b0] = o;
    }
}

// =====================================================================
// Kernel 2: persistent recurrence — IDENTICAL to the 20064us baseline
// except the inner matvec uses fma.rn.f32x2 (half the FFMA issue count).
// =====================================================================
__global__ void __launch_bounds__(NTHR, 1) rec_kernel(
    const float* __restrict__ whh_f, const float* __restrict__ whh_b,
    const float* __restrict__ wih_f, const float* __restrict__ wih_b)
{
    extern __shared__ char smraw[];
    float*  ws   = (float*)smraw;                 // [32 rows][512]  row = p*8+u*4+gate
    float4* hs   = (float4*)(smraw + 65536);      // [128 kq][32 b]
    float*  redA = (float*)(smraw + 131072);      // [8 w][8 q][32 b]
    float*  rsum = redA + 8*8*32;                 // [32]
    float*  red  = rsum + 32;                     // [256]

    const int tid  = threadIdx.x;
    const int w    = tid >> 5;
    const int p    = w & 3;
    const int kh   = w >> 2;
    const int b    = tid & 31;
    const int cell = blockIdx.x >> 6;
    const int g    = blockIdx.x & 63;
    const int jA   = g * 8 + 2 * p;

    const float* whh = cell ? whh_b : whh_f;
    const float* wih = cell ? wih_b : wih_f;

    for (int idx = tid * 4; idx < 32 * 512; idx += NTHR * 4) {
        int rl = idx >> 9, k = idx & 511;
        int p_ = rl >> 3, q = rl & 7, u = q >> 2, gate = q & 3;
        int grow = gate * 512 + g * 8 + 2 * p_ + u;
        *(float4*)&ws[idx] = *(const float4*)&whh[(size_t)grow * 512 + k];
    }
    {   // rowsums of Wih (sub-step-2 scalar-broadcast projection)
        int rl = tid & 31, part = tid >> 5;
        int p_ = rl >> 3, q = rl & 7, u = q >> 2, gate = q & 3;
        int grow = gate * 512 + g * 8 + 2 * p_ + u;
        float s = 0.0f;
        const float* pp = &wih[(size_t)grow * 512 + part * 64];
#pragma unroll 4
        for (int k = 0; k < 64; k += 4) {
            float4 v = *(const float4*)&pp[k];
            s += v.x + v.y + v.z + v.w;
        }
        red[tid] = s;
    }
    __syncthreads();
    if (tid < 32) {
        float s = 0.0f;
#pragma unroll
        for (int q = 0; q < 8; ++q) s += red[tid + 32 * q];
        rsum[tid] = s;
    }
    __syncthreads();
    float rs[8];
#pragma unroll
    for (int q = 0; q < 8; ++q) rs[q] = rsum[p * 8 + q];

    float cst[2] = {0.0f, 0.0f};
    const float4* wr4 = (const float4*)(ws + (p * 8) * 512);
    const bool is_xh = (cell == 1 && jA + 1 == Hh - 1);

    for (int step = 0; step < 2 * Tt; ++step) {
        const int t = step >> 1, sub = step & 1;
        const int rbuf = step & 1, wbuf = rbuf ^ 1;

        float pv[8];
        if (kh == 0) {
            const float* Pt = g_P + ((size_t)t * R4 + (size_t)cell * 2048) * Bb;
#pragma unroll
            for (int q = 0; q < 8; ++q) {
                int u = q >> 2, gate = q & 3;
                pv[q] = Pt[(size_t)(gate * 512 + jA + u) * Bb + b];
            }
        }
        float xh = (sub && kh == 0) ? ldcg1(&g_H[rbuf][1][(Hh - 1) >> 2][b][3]) : 0.0f;

        if (step == 0) {
            float4 z = make_float4(0.f, 0.f, 0.f, 0.f);
            for (int i = tid; i < 128 * 32; i += NTHR) hs[i] = z;
        } else {
            const float4* src = (const float4*)&g_H[rbuf][cell][0][0][0];
            for (int i = tid; i < 128 * 32; i += NTHR) hs[i] = ldcg4(&src[i]);
        }
        __syncthreads();

        // half-k matvec with packed f32x2 FMA (2 MACs/lane/instr)
        u64 acc2[8];
#pragma unroll
        for (int q = 0; q < 8; ++q) acc2[q] = 0ULL;
        const float4* hb = hs + b;
#pragma unroll 4
        for (int kq = kh * 64; kq < kh * 64 + 64; ++kq) {
            F4U2 hv; hv.f4 = hb[kq * 32];
#pragma unroll
            for (int q = 0; q < 8; ++q) {
                F4U2 wv; wv.f4 = wr4[q * 128 + kq];
                fma2(acc2[q], wv.u2[0], hv.u2[0]);
                fma2(acc2[q], wv.u2[1], hv.u2[1]);
            }
        }
        float acc[8];
#pragma unroll
        for (int q = 0; q < 8; ++q) {
            float2 c2 = *(float2*)&acc2[q];
            acc[q] = c2.x + c2.y;
        }
#pragma unroll
        for (int q = 0; q < 8; ++q) redA[(w * 8 + q) * 32 + b] = acc[q];
        __syncthreads();

        if (kh == 0) {
            float h2v[2];
#pragma unroll
            for (int u = 0; u < 2; ++u) {
#pragma unroll
                for (int q = 0; q < 4; ++q) {
                    int qq = u * 4 + q;
                    acc[qq] += redA[((w + 4) * 8 + qq) * 32 + b];
                    acc[qq] += pv[qq] + xh * rs[qq];
                }
                float iv = acc[u*4+0], fv = acc[u*4+1], gv = acc[u*4+2], ov = acc[u*4+3];
                cst[u] = fsig(fv) * cst[u] + fsig(iv) * ftanh(gv);
                h2v[u] = fsig(ov) * ftanh(cst[u]);
            }
            stcg2((float2*)&g_H[wbuf][cell][jA >> 2][b][jA & 3],
                  make_float2(h2v[0], h2v[1]));
            if (is_xh) g_XH[sub][t][b] = h2v[1];
        }

        if (step == 2 * Tt - 1) break;
        __syncthreads();
        if (tid == 0) {
            asm volatile("membar.gl;" ::: "memory");
            atomicAdd(&g_bar, 1u);
            unsigned want = (unsigned)(step + 1) * NBLK;
            unsigned v;
            do {
                asm volatile("ld.acquire.gpu.global.u32 %0,[%1];" : "=r"(v) : "l"(&g_bar));
            } while (v < want);
        }
        __syncthreads();
    }
}

// =====================================================================
// Kernel 3: out = 1.5*u + 0.5*(xh1 + xh2)
// =====================================================================
__global__ __launch_bounds__(256) void epi_kernel(const float* __restrict__ U,
                                                  float* __restrict__ out)
{
    int idx = blockIdx.x * blockDim.x + threadIdx.x;
    if (idx >= Bb * Tt * Dd / 4) return;
    int t = (idx >> 7) & (Tt - 1);
    int b = idx >> 17;
    float s = 0.5f * (g_XH[0][t][b] + g_XH[1][t][b]);
    float4 u = ((const float4*)U)[idx];
    ((float4*)out)[idx] = make_float4(1.5f * u.x + s, 1.5f * u.y + s,
                                      1.5f * u.z + s, 1.5f * u.w + s);
}

extern "C" void kernel_launch(void* const* d_in, const int* in_sizes, int n_in,
                              void* d_out, int out_size) {
    const float* U     = (const float*)d_in[0];
    const float* wih_f = (const float*)d_in[1];
    const float* whh_f = (const float*)d_in[2];
    const float* bih_f = (const float*)d_in[3];
    const float* bhh_f = (const float*)d_in[4];
    const float* wih_b = (const float*)d_in[5];
    const float* whh_b = (const float*)d_in[6];
    const float* bih_b = (const float*)d_in[7];
    const float* bhh_b = (const float*)d_in[8];
    float* out = (float*)d_out;

    const int smem_sz = 65536 + 65536 + (8*8*32 + 32 + NTHR) * 4;
    cudaFuncSetAttribute(rec_kernel, cudaFuncAttributeMaxDynamicSharedMemorySize, smem_sz);

    void* bar_addr = nullptr;
    cudaGetSymbolAddress(&bar_addr, g_bar);
    cudaMemsetAsync(bar_addr, 0, sizeof(unsigned), 0);

    pre_kernel<<<dim3(32, Tt), 256>>>(U, wih_f, wih_b, bih_f, bhh_f, bih_b, bhh_b);
    rec_kernel<<<NBLK, NTHR, smem_sz>>>(whh_f, whh_b, wih_f, wih_b);
    epi_kernel<<<(Bb * Tt * Dd / 4 + 255) / 256, 256>>>(U, out);
}